// round 5
// baseline (speedup 1.0000x reference)
#include <cuda_runtime.h>
#include <cstdint>
#include <cstddef>

#define NE    8
#define HID   2048
#define INTER 2816
#define NTOK  8192
#define MAXENT (NTOK * 2)
#define CAP   16384            // per-expert worst-case rows

// ---------------- scratch (device globals; no runtime allocation) ----------------
__device__ int   g_cursor[NE];
__device__ int   g_list_c[NE * CAP];           // token*2 + slot
__device__ float g_list_w[NE * CAP];
__device__ float c_x[(size_t)NTOK * HID];            // tf32-rounded x   (67 MB)
__device__ float c_w13[(size_t)NE * 2 * INTER * HID];// tf32-rounded w13 (369 MB)
__device__ float c_w2[(size_t)NE * HID * INTER];     // tf32-rounded w2  (184 MB)
__device__ float g_h[(size_t)NE * CAP * INTER];      // padded per-expert h (1.47 GB)
__device__ float g_y[(size_t)MAXENT * HID];          // per-(token,slot) y (134 MB)

// ---------------- helpers ----------------
__device__ __forceinline__ uint32_t f2tf(float x) {
    uint32_t r;
    asm("cvt.rna.tf32.f32 %0, %1;" : "=r"(r) : "f"(x));
    return r;
}
__device__ __forceinline__ uint32_t smem_u32(const void* p) {
    uint32_t a;
    asm("{ .reg .u64 t; cvta.to.shared.u64 t, %1; cvt.u32.u64 %0, t; }" : "=r"(a) : "l"(p));
    return a;
}
__device__ __forceinline__ void cpasync16(uint32_t dst, const void* src, int srcsize) {
    asm volatile("cp.async.cg.shared.global [%0], [%1], 16, %2;"
                 :: "r"(dst), "l"(src), "r"(srcsize) : "memory");
}
#define CP_COMMIT() asm volatile("cp.async.commit_group;" ::: "memory")
#define CP_WAIT2()  asm volatile("cp.async.wait_group 2;" ::: "memory")
#define CP_WAIT1()  asm volatile("cp.async.wait_group 1;" ::: "memory")
#define CP_WAIT0()  asm volatile("cp.async.wait_group 0;" ::: "memory")

__device__ __forceinline__ void mma8(float* d, const uint32_t* a, const uint32_t* b) {
    asm volatile(
        "mma.sync.aligned.m16n8k8.row.col.f32.tf32.tf32.f32 "
        "{%0,%1,%2,%3}, {%4,%5,%6,%7}, {%8,%9}, {%0,%1,%2,%3};\n"
        : "+f"(d[0]), "+f"(d[1]), "+f"(d[2]), "+f"(d[3])
        : "r"(a[0]), "r"(a[1]), "r"(a[2]), "r"(a[3]),
          "r"(b[0]), "r"(b[1]));
}

// swizzled 32-bit smem load from a 128-rowbyte tile: element (r, kword)
#define LDSW(st, r, k) (*(const uint32_t*)((st) + (size_t)(r) * 128 + (((k) * 4) ^ (((r) & 7) << 4))))

#define STAGE_BYTES 32768      // A 16KB + B 16KB
#define NSTAGE 3
#define GEMM_SMEM (NSTAGE * STAGE_BYTES)   // 96 KB -> 2 CTAs/SM

// ---------------- 0a. convert w13 (+ reset cursors) ----------------
__global__ __launch_bounds__(256) void conv_w13_kernel(const float* __restrict__ w13) {
    if (blockIdx.x == 0 && threadIdx.x < NE) g_cursor[threadIdx.x] = 0;
    const size_t n4 = (size_t)NE * 2 * INTER * HID / 4;
    for (size_t i = (size_t)blockIdx.x * blockDim.x + threadIdx.x; i < n4;
         i += (size_t)gridDim.x * blockDim.x) {
        float4 v = ((const float4*)w13)[i];
        uint4 o = make_uint4(f2tf(v.x), f2tf(v.y), f2tf(v.z), f2tf(v.w));
        ((uint4*)c_w13)[i] = o;
    }
}

// ---------------- 0b. convert w2 + x ----------------
__global__ __launch_bounds__(256) void conv_w2x_kernel(const float* __restrict__ w2,
                                                       const float* __restrict__ x) {
    const size_t nw = (size_t)NE * HID * INTER / 4;
    for (size_t i = (size_t)blockIdx.x * blockDim.x + threadIdx.x; i < nw;
         i += (size_t)gridDim.x * blockDim.x) {
        float4 v = ((const float4*)w2)[i];
        ((uint4*)c_w2)[i] = make_uint4(f2tf(v.x), f2tf(v.y), f2tf(v.z), f2tf(v.w));
    }
    const size_t nx = (size_t)NTOK * HID / 4;
    for (size_t i = (size_t)blockIdx.x * blockDim.x + threadIdx.x; i < nx;
         i += (size_t)gridDim.x * blockDim.x) {
        float4 v = ((const float4*)x)[i];
        ((uint4*)c_x)[i] = make_uint4(f2tf(v.x), f2tf(v.y), f2tf(v.z), f2tf(v.w));
    }
}

// ---------------- 1. gating + scatter (fused) ----------------
__global__ __launch_bounds__(256) void gate_kernel(const float* __restrict__ x,
                                                   const float* __restrict__ gw) {
    int warp = threadIdx.x >> 5;
    int lane = threadIdx.x & 31;
    int t = blockIdx.x * 8 + warp;
    if (t >= NTOK) return;

    const float4* xp = (const float4*)(x + (size_t)t * HID);
    float acc[NE];
#pragma unroll
    for (int e = 0; e < NE; e++) acc[e] = 0.f;

    for (int kk = 0; kk < HID / 4; kk += 32) {
        float4 xv = xp[kk + lane];
#pragma unroll
        for (int e = 0; e < NE; e++) {
            float4 g = ((const float4*)(gw + (size_t)e * HID))[kk + lane];
            acc[e] += xv.x * g.x + xv.y * g.y + xv.z * g.z + xv.w * g.w;
        }
    }
#pragma unroll
    for (int e = 0; e < NE; e++) {
#pragma unroll
        for (int o = 16; o > 0; o >>= 1)
            acc[e] += __shfl_xor_sync(0xffffffffu, acc[e], o);
    }
    if (lane == 0) {
        float mx = acc[0];
#pragma unroll
        for (int e = 1; e < NE; e++) mx = fmaxf(mx, acc[e]);
        float p[NE], s = 0.f;
#pragma unroll
        for (int e = 0; e < NE; e++) { p[e] = __expf(acc[e] - mx); s += p[e]; }
        float inv = 1.f / s;
        int i0 = 0; float v0 = p[0];
#pragma unroll
        for (int e = 1; e < NE; e++) if (p[e] > v0) { v0 = p[e]; i0 = e; }
        int i1 = -1; float v1 = -1.f;
#pragma unroll
        for (int e = 0; e < NE; e++) if (e != i0 && p[e] > v1) { v1 = p[e]; i1 = e; }
        int pos0 = atomicAdd(&g_cursor[i0], 1);
        g_list_c[i0 * CAP + pos0] = t * 2;
        g_list_w[i0 * CAP + pos0] = v0 * inv;
        int pos1 = atomicAdd(&g_cursor[i1], 1);
        g_list_c[i1 * CAP + pos1] = t * 2 + 1;
        g_list_w[i1 * CAP + pos1] = v1 * inv;
    }
}

// ---------------- 2. GEMM1: h = silu(X Wg^T) * (X Wu^T) ----------------
// tile 128 rows x (64 g + 64 u cols); 8 warps 4x2; cp.async 3-stage.
#define NS1 (HID / 32)   // 64

__global__ __launch_bounds__(256) void gemm1_kernel() {
    int e = blockIdx.z;
    int cnt = g_cursor[e];
    int rt = blockIdx.y;
    if (rt * 128 >= cnt) return;
    int ct = blockIdx.x;

    extern __shared__ char sm[];
    uint32_t sbase = smem_u32(sm);

    int tid = threadIdx.x;
    int lane = tid & 31, wid = tid >> 5;
    int wm = wid >> 1, wn = wid & 1;

    // loader mapping: 4 A-chunks + 4 B-chunks of 16B per thread per slab
    const float* asrc[4];
    const float* bsrc[4];
    int assz[4];
    uint32_t dsto[4];
#pragma unroll
    for (int i = 0; i < 4; i++) {
        int idx = i * 256 + tid;
        int r = idx >> 3;            // 0..127
        int q = idx & 7;             // 16B chunk in 128B row
        int ridx = rt * 128 + r;
        int tok = (ridx < cnt) ? (g_list_c[e * CAP + ridx] >> 1) : 0;
        asrc[i] = c_x + (size_t)tok * HID + q * 4;
        assz[i] = (ridx < cnt) ? 16 : 0;
        int grow = (r < 64) ? (ct * 64 + r) : (INTER + ct * 64 + (r - 64));
        bsrc[i] = c_w13 + ((size_t)e * 2 * INTER + grow) * HID + q * 4;
        dsto[i] = (uint32_t)(r * 128 + ((q * 16) ^ ((r & 7) << 4)));
    }

    float cg[2][4][4], cu[2][4][4];
#pragma unroll
    for (int mt = 0; mt < 2; mt++)
#pragma unroll
        for (int nt = 0; nt < 4; nt++)
#pragma unroll
            for (int q = 0; q < 4; q++) { cg[mt][nt][q] = 0.f; cu[mt][nt][q] = 0.f; }

    // prologue: slabs 0, 1 into buffers 0, 1
#pragma unroll
    for (int p = 0; p < 2; p++) {
        uint32_t sb = sbase + p * STAGE_BYTES;
        int k0 = p * 32;
#pragma unroll
        for (int i = 0; i < 4; i++) {
            cpasync16(sb + dsto[i], asrc[i] + k0, assz[i]);
            cpasync16(sb + 16384 + dsto[i], bsrc[i] + k0, 16);
        }
        CP_COMMIT();
    }

    int cb = 0;   // buffer index = s % 3
    for (int s = 0; s < NS1; s++) {
        if (s + 2 < NS1) {
            int ib = cb + 2; if (ib >= NSTAGE) ib -= NSTAGE;
            uint32_t sb = sbase + ib * STAGE_BYTES;
            int k0 = (s + 2) * 32;
#pragma unroll
            for (int i = 0; i < 4; i++) {
                cpasync16(sb + dsto[i], asrc[i] + k0, assz[i]);
                cpasync16(sb + 16384 + dsto[i], bsrc[i] + k0, 16);
            }
            CP_COMMIT();
            CP_WAIT2();
        } else if (s + 1 < NS1) {
            CP_WAIT1();
        } else {
            CP_WAIT0();
        }
        __syncthreads();

        const char* stA = sm + cb * STAGE_BYTES;
        const char* stB = stA + 16384;
#pragma unroll
        for (int ks = 0; ks < 4; ks++) {
            int kb = ks * 8 + (lane & 3);
            uint32_t af[2][4];
#pragma unroll
            for (int mt = 0; mt < 2; mt++) {
                int r0 = wm * 32 + mt * 16 + (lane >> 2);
                af[mt][0] = LDSW(stA, r0, kb);     af[mt][1] = LDSW(stA, r0 + 8, kb);
                af[mt][2] = LDSW(stA, r0, kb + 4); af[mt][3] = LDSW(stA, r0 + 8, kb + 4);
            }
#pragma unroll
            for (int nt = 0; nt < 4; nt++) {
                int n = wn * 32 + nt * 8 + (lane >> 2);
                uint32_t bg[2] = { LDSW(stB, n, kb),      LDSW(stB, n, kb + 4) };
                uint32_t bu[2] = { LDSW(stB, n + 64, kb), LDSW(stB, n + 64, kb + 4) };
#pragma unroll
                for (int mt = 0; mt < 2; mt++) {
                    mma8(cg[mt][nt], af[mt], bg);
                    mma8(cu[mt][nt], af[mt], bu);
                }
            }
        }
        __syncthreads();
        cb = (cb + 1 == NSTAGE) ? 0 : cb + 1;
    }

    // epilogue: h = silu(g) * u, stored tf32-rounded
#pragma unroll
    for (int mt = 0; mt < 2; mt++) {
        int rb = wm * 32 + mt * 16 + (lane >> 2);
#pragma unroll
        for (int half = 0; half < 2; half++) {
            int ridx = rt * 128 + rb + half * 8;
            if (ridx < cnt) {
                float* hp = g_h + ((size_t)e * CAP + ridx) * INTER + (size_t)ct * 64;
#pragma unroll
                for (int nt = 0; nt < 4; nt++) {
                    int cc = wn * 32 + nt * 8 + (lane & 3) * 2;
                    float gv0 = cg[mt][nt][half * 2 + 0], gv1 = cg[mt][nt][half * 2 + 1];
                    float uv0 = cu[mt][nt][half * 2 + 0], uv1 = cu[mt][nt][half * 2 + 1];
                    float h0 = gv0 * (1.f / (1.f + __expf(-gv0))) * uv0;
                    float h1 = gv1 * (1.f / (1.f + __expf(-gv1))) * uv1;
                    hp[cc]     = __uint_as_float(f2tf(h0));
                    hp[cc + 1] = __uint_as_float(f2tf(h1));
                }
            }
        }
    }
}

// ---------------- 3. GEMM2: y[c] = w_c * (h W2^T) ----------------
// tile 128x128; 8 warps 4x2, warp 32x64; cp.async 3-stage.
#define NS2 (INTER / 32)  // 88

__global__ __launch_bounds__(256) void gemm2_kernel() {
    int e = blockIdx.z;
    int cnt = g_cursor[e];
    int rt = blockIdx.y;
    if (rt * 128 >= cnt) return;
    int ctn = blockIdx.x;

    extern __shared__ char sm[];
    uint32_t sbase = smem_u32(sm);

    int tid = threadIdx.x;
    int lane = tid & 31, wid = tid >> 5;
    int wm = wid >> 1, wn = wid & 1;

    const float* asrc[4];
    const float* bsrc[4];
    int assz[4];
    uint32_t dsto[4];
#pragma unroll
    for (int i = 0; i < 4; i++) {
        int idx = i * 256 + tid;
        int r = idx >> 3;
        int q = idx & 7;
        int ridx = rt * 128 + r;
        asrc[i] = g_h + ((size_t)e * CAP + ridx) * INTER + q * 4;
        assz[i] = (ridx < cnt) ? 16 : 0;
        bsrc[i] = c_w2 + ((size_t)e * HID + ctn * 128 + r) * INTER + q * 4;
        dsto[i] = (uint32_t)(r * 128 + ((q * 16) ^ ((r & 7) << 4)));
    }

    float acc[2][8][4];
#pragma unroll
    for (int mt = 0; mt < 2; mt++)
#pragma unroll
        for (int nt = 0; nt < 8; nt++)
#pragma unroll
            for (int q = 0; q < 4; q++) acc[mt][nt][q] = 0.f;

    // prologue: slabs 0, 1
#pragma unroll
    for (int p = 0; p < 2; p++) {
        uint32_t sb = sbase + p * STAGE_BYTES;
        int k0 = p * 32;
#pragma unroll
        for (int i = 0; i < 4; i++) {
            cpasync16(sb + dsto[i], asrc[i] + k0, assz[i]);
            cpasync16(sb + 16384 + dsto[i], bsrc[i] + k0, 16);
        }
        CP_COMMIT();
    }

    int cb = 0;
    for (int s = 0; s < NS2; s++) {
        if (s + 2 < NS2) {
            int ib = cb + 2; if (ib >= NSTAGE) ib -= NSTAGE;
            uint32_t sb = sbase + ib * STAGE_BYTES;
            int k0 = (s + 2) * 32;
#pragma unroll
            for (int i = 0; i < 4; i++) {
                cpasync16(sb + dsto[i], asrc[i] + k0, assz[i]);
                cpasync16(sb + 16384 + dsto[i], bsrc[i] + k0, 16);
            }
            CP_COMMIT();
            CP_WAIT2();
        } else if (s + 1 < NS2) {
            CP_WAIT1();
        } else {
            CP_WAIT0();
        }
        __syncthreads();

        const char* stA = sm + cb * STAGE_BYTES;
        const char* stB = stA + 16384;
#pragma unroll
        for (int ks = 0; ks < 4; ks++) {
            int kb = ks * 8 + (lane & 3);
            uint32_t af[2][4];
#pragma unroll
            for (int mt = 0; mt < 2; mt++) {
                int r0 = wm * 32 + mt * 16 + (lane >> 2);
                af[mt][0] = LDSW(stA, r0, kb);     af[mt][1] = LDSW(stA, r0 + 8, kb);
                af[mt][2] = LDSW(stA, r0, kb + 4); af[mt][3] = LDSW(stA, r0 + 8, kb + 4);
            }
#pragma unroll
            for (int nt = 0; nt < 8; nt++) {
                int n = wn * 64 + nt * 8 + (lane >> 2);
                uint32_t bf[2] = { LDSW(stB, n, kb), LDSW(stB, n, kb + 4) };
#pragma unroll
                for (int mt = 0; mt < 2; mt++)
                    mma8(acc[mt][nt], af[mt], bf);
            }
        }
        __syncthreads();
        cb = (cb + 1 == NSTAGE) ? 0 : cb + 1;
    }

    // epilogue: weighted write into per-(token,slot) scratch
#pragma unroll
    for (int mt = 0; mt < 2; mt++) {
        int rb = wm * 32 + mt * 16 + (lane >> 2);
#pragma unroll
        for (int half = 0; half < 2; half++) {
            int ridx = rt * 128 + rb + half * 8;
            if (ridx < cnt) {
                float w = g_list_w[e * CAP + ridx];
                int   c = g_list_c[e * CAP + ridx];
                float* yp = g_y + (size_t)c * HID + (size_t)ctn * 128;
#pragma unroll
                for (int nt = 0; nt < 8; nt++) {
                    int cc = wn * 64 + nt * 8 + (lane & 3) * 2;
                    yp[cc]     = w * acc[mt][nt][half * 2 + 0];
                    yp[cc + 1] = w * acc[mt][nt][half * 2 + 1];
                }
            }
        }
    }
}

// ---------------- 4. combine: out[t] = y[2t] + y[2t+1] ----------------
__global__ void combine_kernel(float* __restrict__ out) {
    size_t idx = (size_t)blockIdx.x * blockDim.x + threadIdx.x;
    const size_t n4 = (size_t)NTOK * HID / 4;
    if (idx >= n4) return;
    size_t t = idx / (HID / 4);
    size_t j = idx % (HID / 4);
    const float4* y4 = (const float4*)g_y;
    float4 a = y4[(t * 2) * (HID / 4) + j];
    float4 b = y4[(t * 2 + 1) * (HID / 4) + j];
    float4 o;
    o.x = a.x + b.x; o.y = a.y + b.y; o.z = a.z + b.z; o.w = a.w + b.w;
    ((float4*)out)[idx] = o;
}

// ---------------- launch ----------------
extern "C" void kernel_launch(void* const* d_in, const int* in_sizes, int n_in,
                              void* d_out, int out_size) {
    const float* x   = (const float*)d_in[0];
    const float* gw  = (const float*)d_in[1];
    const float* w13 = (const float*)d_in[2];
    const float* w2  = (const float*)d_in[3];
    float* out = (float*)d_out;

    cudaFuncSetAttribute(gemm1_kernel, cudaFuncAttributeMaxDynamicSharedMemorySize, GEMM_SMEM);
    cudaFuncSetAttribute(gemm2_kernel, cudaFuncAttributeMaxDynamicSharedMemorySize, GEMM_SMEM);

    conv_w13_kernel<<<2048, 256>>>(w13);                        // launch 0
    conv_w2x_kernel<<<2048, 256>>>(w2, x);                      // launch 1
    gate_kernel<<<NTOK / 8, 256>>>(x, gw);                      // launch 2
    gemm1_kernel<<<dim3(INTER / 64, CAP / 128, NE), 256, GEMM_SMEM>>>();  // launch 3 (ncu)
    gemm2_kernel<<<dim3(HID / 128, CAP / 128, NE), 256, GEMM_SMEM>>>();   // launch 4
    combine_kernel<<<(NTOK * HID / 4) / 256, 256>>>(out);       // launch 5
}

// round 6
// speedup vs baseline: 1.0803x; 1.0803x over previous
#include <cuda_runtime.h>
#include <cstdint>
#include <cstddef>

#define NE    8
#define HID   2048
#define INTER 2816
#define NTOK  8192
#define MAXENT (NTOK * 2)
#define CAP   16384            // per-expert worst-case rows

// ---------------- scratch (device globals; no runtime allocation) ----------------
// All tf32-rounded operands are stored K-PERMUTED: within each 8-element k-group,
// order [0,4,1,5,2,6,3,7] so mma fragment pairs (k, k+4) are adjacent -> LDS.64.
__device__ int   g_cursor[NE];
__device__ int   g_list_c[NE * CAP];           // token*2 + slot
__device__ float g_list_w[NE * CAP];
__device__ float c_x[(size_t)NTOK * HID];            // permuted tf32 x
__device__ float c_w13[(size_t)NE * 2 * INTER * HID];// permuted tf32 w13
__device__ float c_w2[(size_t)NE * HID * INTER];     // permuted tf32 w2
__device__ float g_h[(size_t)NE * CAP * INTER];      // permuted tf32 h
__device__ float g_y[(size_t)MAXENT * HID];          // natural layout y

// ---------------- helpers ----------------
__device__ __forceinline__ uint32_t f2tf(float x) {
    uint32_t r;
    asm("cvt.rna.tf32.f32 %0, %1;" : "=r"(r) : "f"(x));
    return r;
}
__device__ __forceinline__ uint32_t smem_u32(const void* p) {
    uint32_t a;
    asm("{ .reg .u64 t; cvta.to.shared.u64 t, %1; cvt.u32.u64 %0, t; }" : "=r"(a) : "l"(p));
    return a;
}
__device__ __forceinline__ void cpasync16(uint32_t dst, const void* src, int srcsize) {
    asm volatile("cp.async.cg.shared.global [%0], [%1], 16, %2;"
                 :: "r"(dst), "l"(src), "r"(srcsize) : "memory");
}
#define CP_COMMIT() asm volatile("cp.async.commit_group;" ::: "memory")
#define CP_WAIT1()  asm volatile("cp.async.wait_group 1;" ::: "memory")
#define CP_WAIT0()  asm volatile("cp.async.wait_group 0;" ::: "memory")

__device__ __forceinline__ void mma8(float* d, const uint32_t* a, const uint32_t* b) {
    asm volatile(
        "mma.sync.aligned.m16n8k8.row.col.f32.tf32.tf32.f32 "
        "{%0,%1,%2,%3}, {%4,%5,%6,%7}, {%8,%9}, {%0,%1,%2,%3};\n"
        : "+f"(d[0]), "+f"(d[1]), "+f"(d[2]), "+f"(d[3])
        : "r"(a[0]), "r"(a[1]), "r"(a[2]), "r"(a[3]),
          "r"(b[0]), "r"(b[1]));
}

// 64-bit swizzled fragment load: row r, k-group ks, pair index li (0..3)
// returns {orig[ks*8+li], orig[ks*8+li+4]} thanks to the k-interleave permute
#define LD64(st, r, ks, li) \
    (*(const uint2*)((st) + (size_t)(r) * 128 + ((((ks) * 32 + (li) * 8)) ^ (((r) & 7) << 4))))

#define STAGE_BYTES 32768      // A 16KB + B 16KB
#define GEMM_SMEM (2 * STAGE_BYTES)

// ---------------- 0a. convert+permute w13 (+ reset cursors) ----------------
__global__ __launch_bounds__(256) void conv_w13_kernel(const float* __restrict__ w13) {
    if (blockIdx.x == 0 && threadIdx.x < NE) g_cursor[threadIdx.x] = 0;
    const size_t ng = (size_t)NE * 2 * INTER * HID / 8;
    for (size_t g = (size_t)blockIdx.x * blockDim.x + threadIdx.x; g < ng;
         g += (size_t)gridDim.x * blockDim.x) {
        const float4* src = (const float4*)(w13 + g * 8);
        float4 lo = src[0], hi = src[1];
        uint4 o0 = make_uint4(f2tf(lo.x), f2tf(hi.x), f2tf(lo.y), f2tf(hi.y));
        uint4 o1 = make_uint4(f2tf(lo.z), f2tf(hi.z), f2tf(lo.w), f2tf(hi.w));
        ((uint4*)c_w13)[g * 2]     = o0;
        ((uint4*)c_w13)[g * 2 + 1] = o1;
    }
}

// ---------------- 0b. convert+permute w2 + x ----------------
__global__ __launch_bounds__(256) void conv_w2x_kernel(const float* __restrict__ w2,
                                                       const float* __restrict__ x) {
    const size_t nw = (size_t)NE * HID * INTER / 8;
    for (size_t g = (size_t)blockIdx.x * blockDim.x + threadIdx.x; g < nw;
         g += (size_t)gridDim.x * blockDim.x) {
        const float4* src = (const float4*)(w2 + g * 8);
        float4 lo = src[0], hi = src[1];
        ((uint4*)c_w2)[g * 2]     = make_uint4(f2tf(lo.x), f2tf(hi.x), f2tf(lo.y), f2tf(hi.y));
        ((uint4*)c_w2)[g * 2 + 1] = make_uint4(f2tf(lo.z), f2tf(hi.z), f2tf(lo.w), f2tf(hi.w));
    }
    const size_t nx = (size_t)NTOK * HID / 8;
    for (size_t g = (size_t)blockIdx.x * blockDim.x + threadIdx.x; g < nx;
         g += (size_t)gridDim.x * blockDim.x) {
        const float4* src = (const float4*)(x + g * 8);
        float4 lo = src[0], hi = src[1];
        ((uint4*)c_x)[g * 2]     = make_uint4(f2tf(lo.x), f2tf(hi.x), f2tf(lo.y), f2tf(hi.y));
        ((uint4*)c_x)[g * 2 + 1] = make_uint4(f2tf(lo.z), f2tf(hi.z), f2tf(lo.w), f2tf(hi.w));
    }
}

// ---------------- 1. gating + scatter (fused) ----------------
__global__ __launch_bounds__(256) void gate_kernel(const float* __restrict__ x,
                                                   const float* __restrict__ gw) {
    int warp = threadIdx.x >> 5;
    int lane = threadIdx.x & 31;
    int t = blockIdx.x * 8 + warp;
    if (t >= NTOK) return;

    const float4* xp = (const float4*)(x + (size_t)t * HID);
    float acc[NE];
#pragma unroll
    for (int e = 0; e < NE; e++) acc[e] = 0.f;

    for (int kk = 0; kk < HID / 4; kk += 32) {
        float4 xv = xp[kk + lane];
#pragma unroll
        for (int e = 0; e < NE; e++) {
            float4 g = ((const float4*)(gw + (size_t)e * HID))[kk + lane];
            acc[e] += xv.x * g.x + xv.y * g.y + xv.z * g.z + xv.w * g.w;
        }
    }
#pragma unroll
    for (int e = 0; e < NE; e++) {
#pragma unroll
        for (int o = 16; o > 0; o >>= 1)
            acc[e] += __shfl_xor_sync(0xffffffffu, acc[e], o);
    }
    if (lane == 0) {
        float mx = acc[0];
#pragma unroll
        for (int e = 1; e < NE; e++) mx = fmaxf(mx, acc[e]);
        float p[NE], s = 0.f;
#pragma unroll
        for (int e = 0; e < NE; e++) { p[e] = __expf(acc[e] - mx); s += p[e]; }
        float inv = 1.f / s;
        int i0 = 0; float v0 = p[0];
#pragma unroll
        for (int e = 1; e < NE; e++) if (p[e] > v0) { v0 = p[e]; i0 = e; }
        int i1 = -1; float v1 = -1.f;
#pragma unroll
        for (int e = 0; e < NE; e++) if (e != i0 && p[e] > v1) { v1 = p[e]; i1 = e; }
        int pos0 = atomicAdd(&g_cursor[i0], 1);
        g_list_c[i0 * CAP + pos0] = t * 2;
        g_list_w[i0 * CAP + pos0] = v0 * inv;
        int pos1 = atomicAdd(&g_cursor[i1], 1);
        g_list_c[i1 * CAP + pos1] = t * 2 + 1;
        g_list_w[i1 * CAP + pos1] = v1 * inv;
    }
}

// ---------------- 2. GEMM1: h = silu(X Wg^T) * (X Wu^T) ----------------
// tile 128 rows x (64 g + 64 u cols); 8 warps 4x2; cp.async 2-stage; LDS.64 fragments.
#define NS1 (HID / 32)   // 64

__global__ __launch_bounds__(256) void gemm1_kernel() {
    int e = blockIdx.z;
    int cnt = g_cursor[e];
    int rt = blockIdx.y;
    if (rt * 128 >= cnt) return;
    int ct = blockIdx.x;

    extern __shared__ char sm[];
    uint32_t sbase = smem_u32(sm);

    int tid = threadIdx.x;
    int lane = tid & 31, wid = tid >> 5;
    int wm = wid >> 1, wn = wid & 1;

    // loader mapping: 4 A-chunks + 4 B-chunks of 16B per thread per slab
    const float* asrc[4];
    const float* bsrc[4];
    int assz[4];
    uint32_t dsto[4];
#pragma unroll
    for (int i = 0; i < 4; i++) {
        int idx = i * 256 + tid;
        int r = idx >> 3;            // 0..127
        int q = idx & 7;             // 16B chunk in 128B row
        int ridx = rt * 128 + r;
        int tok = (ridx < cnt) ? (g_list_c[e * CAP + ridx] >> 1) : 0;
        asrc[i] = c_x + (size_t)tok * HID + q * 4;
        assz[i] = (ridx < cnt) ? 16 : 0;
        int grow = (r < 64) ? (ct * 64 + r) : (INTER + ct * 64 + (r - 64));
        bsrc[i] = c_w13 + ((size_t)e * 2 * INTER + grow) * HID + q * 4;
        dsto[i] = (uint32_t)(r * 128 + ((q * 16) ^ ((r & 7) << 4)));
    }

    float cg[2][4][4], cu[2][4][4];
#pragma unroll
    for (int mt = 0; mt < 2; mt++)
#pragma unroll
        for (int nt = 0; nt < 4; nt++)
#pragma unroll
            for (int q = 0; q < 4; q++) { cg[mt][nt][q] = 0.f; cu[mt][nt][q] = 0.f; }

    // prologue: slab 0
#pragma unroll
    for (int i = 0; i < 4; i++) {
        cpasync16(sbase + dsto[i], asrc[i], assz[i]);
        cpasync16(sbase + 16384 + dsto[i], bsrc[i], 16);
    }
    CP_COMMIT();

    int li = lane & 3;
    for (int s = 0; s < NS1; s++) {
        if (s + 1 < NS1) {
            uint32_t sb = sbase + ((s + 1) & 1) * STAGE_BYTES;
            int k0 = (s + 1) * 32;
#pragma unroll
            for (int i = 0; i < 4; i++) {
                cpasync16(sb + dsto[i], asrc[i] + k0, assz[i]);
                cpasync16(sb + 16384 + dsto[i], bsrc[i] + k0, 16);
            }
            CP_COMMIT();
            CP_WAIT1();
        } else {
            CP_WAIT0();
        }
        __syncthreads();

        const char* stA = sm + (s & 1) * STAGE_BYTES;
        const char* stB = stA + 16384;
#pragma unroll
        for (int ks = 0; ks < 4; ks++) {
            uint32_t af[2][4];
#pragma unroll
            for (int mt = 0; mt < 2; mt++) {
                int r0 = wm * 32 + mt * 16 + (lane >> 2);
                uint2 va  = LD64(stA, r0,     ks, li);
                uint2 va8 = LD64(stA, r0 + 8, ks, li);
                af[mt][0] = va.x; af[mt][1] = va8.x; af[mt][2] = va.y; af[mt][3] = va8.y;
            }
#pragma unroll
            for (int nt = 0; nt < 4; nt++) {
                int n = wn * 32 + nt * 8 + (lane >> 2);
                uint2 vg = LD64(stB, n,      ks, li);
                uint2 vu = LD64(stB, n + 64, ks, li);
                uint32_t bg[2] = { vg.x, vg.y };
                uint32_t bu[2] = { vu.x, vu.y };
#pragma unroll
                for (int mt = 0; mt < 2; mt++) {
                    mma8(cg[mt][nt], af[mt], bg);
                    mma8(cu[mt][nt], af[mt], bu);
                }
            }
        }
        __syncthreads();
    }

    // epilogue: h = silu(g) * u, stored tf32-rounded in PERMUTED k order.
    // thread owns original columns (wi, wi+1); permuted positions (p, p+2).
    int wi = (lane & 3) * 2;
    int pp = (wi < 4) ? (wi * 2) : ((wi - 4) * 2 + 1);
#pragma unroll
    for (int mt = 0; mt < 2; mt++) {
        int rb = wm * 32 + mt * 16 + (lane >> 2);
#pragma unroll
        for (int half = 0; half < 2; half++) {
            int ridx = rt * 128 + rb + half * 8;
            if (ridx < cnt) {
                float* hp = g_h + ((size_t)e * CAP + ridx) * INTER + (size_t)ct * 64;
#pragma unroll
                for (int nt = 0; nt < 4; nt++) {
                    int cb = wn * 32 + nt * 8;
                    float gv0 = cg[mt][nt][half * 2 + 0], gv1 = cg[mt][nt][half * 2 + 1];
                    float uv0 = cu[mt][nt][half * 2 + 0], uv1 = cu[mt][nt][half * 2 + 1];
                    float h0 = gv0 * (1.f / (1.f + __expf(-gv0))) * uv0;
                    float h1 = gv1 * (1.f / (1.f + __expf(-gv1))) * uv1;
                    hp[cb + pp]     = __uint_as_float(f2tf(h0));
                    hp[cb + pp + 2] = __uint_as_float(f2tf(h1));
                }
            }
        }
    }
}

// ---------------- 3. GEMM2: y[c] = w_c * (h W2^T) ----------------
// tile 128x128; 8 warps 4x2, warp 32x64; cp.async 2-stage; LDS.64 fragments.
#define NS2 (INTER / 32)  // 88

__global__ __launch_bounds__(256) void gemm2_kernel() {
    int e = blockIdx.z;
    int cnt = g_cursor[e];
    int rt = blockIdx.y;
    if (rt * 128 >= cnt) return;
    int ctn = blockIdx.x;

    extern __shared__ char sm[];
    uint32_t sbase = smem_u32(sm);

    int tid = threadIdx.x;
    int lane = tid & 31, wid = tid >> 5;
    int wm = wid >> 1, wn = wid & 1;

    const float* asrc[4];
    const float* bsrc[4];
    int assz[4];
    uint32_t dsto[4];
#pragma unroll
    for (int i = 0; i < 4; i++) {
        int idx = i * 256 + tid;
        int r = idx >> 3;
        int q = idx & 7;
        int ridx = rt * 128 + r;
        asrc[i] = g_h + ((size_t)e * CAP + ridx) * INTER + q * 4;
        assz[i] = (ridx < cnt) ? 16 : 0;
        bsrc[i] = c_w2 + ((size_t)e * HID + ctn * 128 + r) * INTER + q * 4;
        dsto[i] = (uint32_t)(r * 128 + ((q * 16) ^ ((r & 7) << 4)));
    }

    float acc[2][8][4];
#pragma unroll
    for (int mt = 0; mt < 2; mt++)
#pragma unroll
        for (int nt = 0; nt < 8; nt++)
#pragma unroll
            for (int q = 0; q < 4; q++) acc[mt][nt][q] = 0.f;

#pragma unroll
    for (int i = 0; i < 4; i++) {
        cpasync16(sbase + dsto[i], asrc[i], assz[i]);
        cpasync16(sbase + 16384 + dsto[i], bsrc[i], 16);
    }
    CP_COMMIT();

    int li = lane & 3;
    for (int s = 0; s < NS2; s++) {
        if (s + 1 < NS2) {
            uint32_t sb = sbase + ((s + 1) & 1) * STAGE_BYTES;
            int k0 = (s + 1) * 32;
#pragma unroll
            for (int i = 0; i < 4; i++) {
                cpasync16(sb + dsto[i], asrc[i] + k0, assz[i]);
                cpasync16(sb + 16384 + dsto[i], bsrc[i] + k0, 16);
            }
            CP_COMMIT();
            CP_WAIT1();
        } else {
            CP_WAIT0();
        }
        __syncthreads();

        const char* stA = sm + (s & 1) * STAGE_BYTES;
        const char* stB = stA + 16384;
#pragma unroll
        for (int ks = 0; ks < 4; ks++) {
            uint32_t af[2][4];
#pragma unroll
            for (int mt = 0; mt < 2; mt++) {
                int r0 = wm * 32 + mt * 16 + (lane >> 2);
                uint2 va  = LD64(stA, r0,     ks, li);
                uint2 va8 = LD64(stA, r0 + 8, ks, li);
                af[mt][0] = va.x; af[mt][1] = va8.x; af[mt][2] = va.y; af[mt][3] = va8.y;
            }
#pragma unroll
            for (int nt = 0; nt < 8; nt++) {
                int n = wn * 64 + nt * 8 + (lane >> 2);
                uint2 vb = LD64(stB, n, ks, li);
                uint32_t bf[2] = { vb.x, vb.y };
#pragma unroll
                for (int mt = 0; mt < 2; mt++)
                    mma8(acc[mt][nt], af[mt], bf);
            }
        }
        __syncthreads();
    }

    // epilogue: weighted write into per-(token,slot) scratch (natural layout)
#pragma unroll
    for (int mt = 0; mt < 2; mt++) {
        int rb = wm * 32 + mt * 16 + (lane >> 2);
#pragma unroll
        for (int half = 0; half < 2; half++) {
            int ridx = rt * 128 + rb + half * 8;
            if (ridx < cnt) {
                float w = g_list_w[e * CAP + ridx];
                int   c = g_list_c[e * CAP + ridx];
                float* yp = g_y + (size_t)c * HID + (size_t)ctn * 128;
#pragma unroll
                for (int nt = 0; nt < 8; nt++) {
                    int cc = wn * 64 + nt * 8 + (lane & 3) * 2;
                    yp[cc]     = w * acc[mt][nt][half * 2 + 0];
                    yp[cc + 1] = w * acc[mt][nt][half * 2 + 1];
                }
            }
        }
    }
}

// ---------------- 4. combine: out[t] = y[2t] + y[2t+1] ----------------
__global__ void combine_kernel(float* __restrict__ out) {
    size_t idx = (size_t)blockIdx.x * blockDim.x + threadIdx.x;
    const size_t n4 = (size_t)NTOK * HID / 4;
    if (idx >= n4) return;
    size_t t = idx / (HID / 4);
    size_t j = idx % (HID / 4);
    const float4* y4 = (const float4*)g_y;
    float4 a = y4[(t * 2) * (HID / 4) + j];
    float4 b = y4[(t * 2 + 1) * (HID / 4) + j];
    float4 o;
    o.x = a.x + b.x; o.y = a.y + b.y; o.z = a.z + b.z; o.w = a.w + b.w;
    ((float4*)out)[idx] = o;
}

// ---------------- launch ----------------
extern "C" void kernel_launch(void* const* d_in, const int* in_sizes, int n_in,
                              void* d_out, int out_size) {
    const float* x   = (const float*)d_in[0];
    const float* gw  = (const float*)d_in[1];
    const float* w13 = (const float*)d_in[2];
    const float* w2  = (const float*)d_in[3];
    float* out = (float*)d_out;

    cudaFuncSetAttribute(gemm1_kernel, cudaFuncAttributeMaxDynamicSharedMemorySize, GEMM_SMEM);
    cudaFuncSetAttribute(gemm2_kernel, cudaFuncAttributeMaxDynamicSharedMemorySize, GEMM_SMEM);

    conv_w13_kernel<<<2048, 256>>>(w13);                        // launch 0
    conv_w2x_kernel<<<2048, 256>>>(w2, x);                      // launch 1
    gate_kernel<<<NTOK / 8, 256>>>(x, gw);                      // launch 2
    gemm1_kernel<<<dim3(INTER / 64, CAP / 128, NE), 256, GEMM_SMEM>>>();  // launch 3 (ncu)
    gemm2_kernel<<<dim3(HID / 128, CAP / 128, NE), 256, GEMM_SMEM>>>();   // launch 4
    combine_kernel<<<(NTOK * HID / 4) / 256, 256>>>(out);       // launch 5
}

// round 7
// speedup vs baseline: 1.8834x; 1.7435x over previous
#include <cuda_runtime.h>
#include <cuda_fp16.h>
#include <cstdint>
#include <cstddef>

#define NE    8
#define HID   2048
#define INTER 2816
#define NTOK  8192
#define MAXENT (NTOK * 2)
#define CAP   16384            // per-expert worst-case rows

// ---------------- scratch (device globals; no runtime allocation) ----------------
__device__ int    g_cursor[NE];
__device__ int    g_list_c[NE * CAP];          // token*2 + slot
__device__ float  g_list_w[NE * CAP];
__device__ __half c_x[(size_t)NTOK * HID];             // fp16 x   (33 MB)
__device__ __half c_w13[(size_t)NE * 2 * INTER * HID]; // fp16 w13 (184 MB)
__device__ __half c_w2[(size_t)NE * HID * INTER];      // fp16 w2  (92 MB)
__device__ __half g_h[(size_t)NE * CAP * INTER];       // fp16 h   (738 MB)
__device__ float  g_y[(size_t)MAXENT * HID];           // fp32 y   (134 MB)

// ---------------- helpers ----------------
__device__ __forceinline__ uint32_t smem_u32(const void* p) {
    uint32_t a;
    asm("{ .reg .u64 t; cvta.to.shared.u64 t, %1; cvt.u32.u64 %0, t; }" : "=r"(a) : "l"(p));
    return a;
}
__device__ __forceinline__ void cpasync16(uint32_t dst, const void* src, int srcsize) {
    asm volatile("cp.async.cg.shared.global [%0], [%1], 16, %2;"
                 :: "r"(dst), "l"(src), "r"(srcsize) : "memory");
}
#define CP_COMMIT() asm volatile("cp.async.commit_group;" ::: "memory")
#define CP_WAIT1()  asm volatile("cp.async.wait_group 1;" ::: "memory")
#define CP_WAIT0()  asm volatile("cp.async.wait_group 0;" ::: "memory")

// fp16 MMA, fp32 accumulate: D(16x8) += A(16x16) * B(8x16)^T
__device__ __forceinline__ void mma16(float* d, const uint32_t* a, const uint32_t* b) {
    asm volatile(
        "mma.sync.aligned.m16n8k16.row.col.f32.f16.f16.f32 "
        "{%0,%1,%2,%3}, {%4,%5,%6,%7}, {%8,%9}, {%0,%1,%2,%3};\n"
        : "+f"(d[0]), "+f"(d[1]), "+f"(d[2]), "+f"(d[3])
        : "r"(a[0]), "r"(a[1]), "r"(a[2]), "r"(a[3]),
          "r"(b[0]), "r"(b[1]));
}

__device__ __forceinline__ uint32_t h2u(__half2 h) {
    return *(const uint32_t*)&h;
}

// swizzled 32-bit smem fragment load: row r (128B rows), k16-group ks, lane pair li,
// hf=0 -> halves {k,k+1} at k=ks*16+li*2 ; hf=1 -> halves {k+8,k+9}
#define LDH(st, r, ks, li, hf) \
    (*(const uint32_t*)((st) + (size_t)(r) * 128 + (((ks) * 32 + (li) * 4 + (hf) * 16) ^ (((r) & 7) << 4))))

#define STAGE_BYTES 32768      // A 16KB + B 16KB (128 rows x 128B, k-slab = 64 halves)
#define GEMM_SMEM (2 * STAGE_BYTES)   // 64 KB -> 2 CTAs/SM

// ---------------- 0a. convert w13 -> fp16 (+ reset cursors) ----------------
__global__ __launch_bounds__(256) void conv_w13_kernel(const float* __restrict__ w13) {
    if (blockIdx.x == 0 && threadIdx.x < NE) g_cursor[threadIdx.x] = 0;
    const size_t ng = (size_t)NE * 2 * INTER * HID / 8;
    for (size_t g = (size_t)blockIdx.x * blockDim.x + threadIdx.x; g < ng;
         g += (size_t)gridDim.x * blockDim.x) {
        const float4* src = (const float4*)(w13 + g * 8);
        float4 lo = src[0], hi = src[1];
        uint4 o;
        o.x = h2u(__floats2half2_rn(lo.x, lo.y));
        o.y = h2u(__floats2half2_rn(lo.z, lo.w));
        o.z = h2u(__floats2half2_rn(hi.x, hi.y));
        o.w = h2u(__floats2half2_rn(hi.z, hi.w));
        ((uint4*)c_w13)[g] = o;
    }
}

// ---------------- 0b. convert w2 + x -> fp16 ----------------
__global__ __launch_bounds__(256) void conv_w2x_kernel(const float* __restrict__ w2,
                                                       const float* __restrict__ x) {
    const size_t nw = (size_t)NE * HID * INTER / 8;
    for (size_t g = (size_t)blockIdx.x * blockDim.x + threadIdx.x; g < nw;
         g += (size_t)gridDim.x * blockDim.x) {
        const float4* src = (const float4*)(w2 + g * 8);
        float4 lo = src[0], hi = src[1];
        uint4 o;
        o.x = h2u(__floats2half2_rn(lo.x, lo.y));
        o.y = h2u(__floats2half2_rn(lo.z, lo.w));
        o.z = h2u(__floats2half2_rn(hi.x, hi.y));
        o.w = h2u(__floats2half2_rn(hi.z, hi.w));
        ((uint4*)c_w2)[g] = o;
    }
    const size_t nx = (size_t)NTOK * HID / 8;
    for (size_t g = (size_t)blockIdx.x * blockDim.x + threadIdx.x; g < nx;
         g += (size_t)gridDim.x * blockDim.x) {
        const float4* src = (const float4*)(x + g * 8);
        float4 lo = src[0], hi = src[1];
        uint4 o;
        o.x = h2u(__floats2half2_rn(lo.x, lo.y));
        o.y = h2u(__floats2half2_rn(lo.z, lo.w));
        o.z = h2u(__floats2half2_rn(hi.x, hi.y));
        o.w = h2u(__floats2half2_rn(hi.z, hi.w));
        ((uint4*)c_x)[g] = o;
    }
}

// ---------------- 1. gating + scatter (fused, fp32) ----------------
__global__ __launch_bounds__(256) void gate_kernel(const float* __restrict__ x,
                                                   const float* __restrict__ gw) {
    int warp = threadIdx.x >> 5;
    int lane = threadIdx.x & 31;
    int t = blockIdx.x * 8 + warp;
    if (t >= NTOK) return;

    const float4* xp = (const float4*)(x + (size_t)t * HID);
    float acc[NE];
#pragma unroll
    for (int e = 0; e < NE; e++) acc[e] = 0.f;

    for (int kk = 0; kk < HID / 4; kk += 32) {
        float4 xv = xp[kk + lane];
#pragma unroll
        for (int e = 0; e < NE; e++) {
            float4 g = ((const float4*)(gw + (size_t)e * HID))[kk + lane];
            acc[e] += xv.x * g.x + xv.y * g.y + xv.z * g.z + xv.w * g.w;
        }
    }
#pragma unroll
    for (int e = 0; e < NE; e++) {
#pragma unroll
        for (int o = 16; o > 0; o >>= 1)
            acc[e] += __shfl_xor_sync(0xffffffffu, acc[e], o);
    }
    if (lane == 0) {
        float mx = acc[0];
#pragma unroll
        for (int e = 1; e < NE; e++) mx = fmaxf(mx, acc[e]);
        float p[NE], s = 0.f;
#pragma unroll
        for (int e = 0; e < NE; e++) { p[e] = __expf(acc[e] - mx); s += p[e]; }
        float inv = 1.f / s;
        int i0 = 0; float v0 = p[0];
#pragma unroll
        for (int e = 1; e < NE; e++) if (p[e] > v0) { v0 = p[e]; i0 = e; }
        int i1 = -1; float v1 = -1.f;
#pragma unroll
        for (int e = 0; e < NE; e++) if (e != i0 && p[e] > v1) { v1 = p[e]; i1 = e; }
        int pos0 = atomicAdd(&g_cursor[i0], 1);
        g_list_c[i0 * CAP + pos0] = t * 2;
        g_list_w[i0 * CAP + pos0] = v0 * inv;
        int pos1 = atomicAdd(&g_cursor[i1], 1);
        g_list_c[i1 * CAP + pos1] = t * 2 + 1;
        g_list_w[i1 * CAP + pos1] = v1 * inv;
    }
}

// ---------------- 2. GEMM1: h = silu(X Wg^T) * (X Wu^T), fp16 MMA ----------------
// tile 128 rows x (64 g + 64 u cols); 8 warps 4x2; cp.async 2-stage; k-slab 64.
#define NS1 (HID / 64)   // 32

__global__ __launch_bounds__(256) void gemm1_kernel() {
    int e = blockIdx.z;
    int cnt = g_cursor[e];
    int rt = blockIdx.y;
    if (rt * 128 >= cnt) return;
    int ct = blockIdx.x;

    extern __shared__ char sm[];
    uint32_t sbase = smem_u32(sm);

    int tid = threadIdx.x;
    int lane = tid & 31, wid = tid >> 5;
    int wm = wid >> 1, wn = wid & 1;

    // loader mapping: 4 A-chunks + 4 B-chunks of 16B (8 halves) per thread per slab
    const __half* asrc[4];
    const __half* bsrc[4];
    int assz[4];
    uint32_t dsto[4];
#pragma unroll
    for (int i = 0; i < 4; i++) {
        int idx = i * 256 + tid;
        int r = idx >> 3;            // 0..127
        int q = idx & 7;             // 16B chunk in 128B row
        int ridx = rt * 128 + r;
        int tok = (ridx < cnt) ? (g_list_c[e * CAP + ridx] >> 1) : 0;
        asrc[i] = c_x + (size_t)tok * HID + q * 8;
        assz[i] = (ridx < cnt) ? 16 : 0;
        int grow = (r < 64) ? (ct * 64 + r) : (INTER + ct * 64 + (r - 64));
        bsrc[i] = c_w13 + ((size_t)e * 2 * INTER + grow) * HID + q * 8;
        dsto[i] = (uint32_t)(r * 128 + ((q * 16) ^ ((r & 7) << 4)));
    }

    float cg[2][4][4], cu[2][4][4];
#pragma unroll
    for (int mt = 0; mt < 2; mt++)
#pragma unroll
        for (int nt = 0; nt < 4; nt++)
#pragma unroll
            for (int q = 0; q < 4; q++) { cg[mt][nt][q] = 0.f; cu[mt][nt][q] = 0.f; }

    // prologue: slab 0
#pragma unroll
    for (int i = 0; i < 4; i++) {
        cpasync16(sbase + dsto[i], asrc[i], assz[i]);
        cpasync16(sbase + 16384 + dsto[i], bsrc[i], 16);
    }
    CP_COMMIT();

    int li = lane & 3;
    for (int s = 0; s < NS1; s++) {
        if (s + 1 < NS1) {
            uint32_t sb = sbase + ((s + 1) & 1) * STAGE_BYTES;
            int k0 = (s + 1) * 64;
#pragma unroll
            for (int i = 0; i < 4; i++) {
                cpasync16(sb + dsto[i], asrc[i] + k0, assz[i]);
                cpasync16(sb + 16384 + dsto[i], bsrc[i] + k0, 16);
            }
            CP_COMMIT();
            CP_WAIT1();
        } else {
            CP_WAIT0();
        }
        __syncthreads();

        const char* stA = sm + (s & 1) * STAGE_BYTES;
        const char* stB = stA + 16384;
#pragma unroll
        for (int ks = 0; ks < 4; ks++) {
            uint32_t af[2][4];
#pragma unroll
            for (int mt = 0; mt < 2; mt++) {
                int r0 = wm * 32 + mt * 16 + (lane >> 2);
                af[mt][0] = LDH(stA, r0,     ks, li, 0);
                af[mt][1] = LDH(stA, r0 + 8, ks, li, 0);
                af[mt][2] = LDH(stA, r0,     ks, li, 1);
                af[mt][3] = LDH(stA, r0 + 8, ks, li, 1);
            }
#pragma unroll
            for (int nt = 0; nt < 4; nt++) {
                int n = wn * 32 + nt * 8 + (lane >> 2);
                uint32_t bg[2] = { LDH(stB, n,      ks, li, 0), LDH(stB, n,      ks, li, 1) };
                uint32_t bu[2] = { LDH(stB, n + 64, ks, li, 0), LDH(stB, n + 64, ks, li, 1) };
#pragma unroll
                for (int mt = 0; mt < 2; mt++) {
                    mma16(cg[mt][nt], af[mt], bg);
                    mma16(cu[mt][nt], af[mt], bu);
                }
            }
        }
        __syncthreads();
    }

    // epilogue: h = silu(g) * u, stored fp16 (half2 per thread pair)
#pragma unroll
    for (int mt = 0; mt < 2; mt++) {
        int rb = wm * 32 + mt * 16 + (lane >> 2);
#pragma unroll
        for (int half = 0; half < 2; half++) {
            int ridx = rt * 128 + rb + half * 8;
            if (ridx < cnt) {
                __half* hp = g_h + ((size_t)e * CAP + ridx) * INTER + (size_t)ct * 64;
#pragma unroll
                for (int nt = 0; nt < 4; nt++) {
                    int cc = wn * 32 + nt * 8 + (lane & 3) * 2;
                    float gv0 = cg[mt][nt][half * 2 + 0], gv1 = cg[mt][nt][half * 2 + 1];
                    float uv0 = cu[mt][nt][half * 2 + 0], uv1 = cu[mt][nt][half * 2 + 1];
                    float h0 = gv0 * (1.f / (1.f + __expf(-gv0))) * uv0;
                    float h1 = gv1 * (1.f / (1.f + __expf(-gv1))) * uv1;
                    *(__half2*)(hp + cc) = __floats2half2_rn(h0, h1);
                }
            }
        }
    }
}

// ---------------- 3. GEMM2: y[c] = w_c * (h W2^T), fp16 MMA ----------------
// tile 128x128; 8 warps 4x2, warp 32x64; cp.async 2-stage; k-slab 64.
#define NS2 (INTER / 64)  // 44

__global__ __launch_bounds__(256) void gemm2_kernel() {
    int e = blockIdx.z;
    int cnt = g_cursor[e];
    int rt = blockIdx.y;
    if (rt * 128 >= cnt) return;
    int ctn = blockIdx.x;

    extern __shared__ char sm[];
    uint32_t sbase = smem_u32(sm);

    int tid = threadIdx.x;
    int lane = tid & 31, wid = tid >> 5;
    int wm = wid >> 1, wn = wid & 1;

    const __half* asrc[4];
    const __half* bsrc[4];
    int assz[4];
    uint32_t dsto[4];
#pragma unroll
    for (int i = 0; i < 4; i++) {
        int idx = i * 256 + tid;
        int r = idx >> 3;
        int q = idx & 7;
        int ridx = rt * 128 + r;
        asrc[i] = g_h + ((size_t)e * CAP + ridx) * INTER + q * 8;
        assz[i] = (ridx < cnt) ? 16 : 0;
        bsrc[i] = c_w2 + ((size_t)e * HID + ctn * 128 + r) * INTER + q * 8;
        dsto[i] = (uint32_t)(r * 128 + ((q * 16) ^ ((r & 7) << 4)));
    }

    float acc[2][8][4];
#pragma unroll
    for (int mt = 0; mt < 2; mt++)
#pragma unroll
        for (int nt = 0; nt < 8; nt++)
#pragma unroll
            for (int q = 0; q < 4; q++) acc[mt][nt][q] = 0.f;

#pragma unroll
    for (int i = 0; i < 4; i++) {
        cpasync16(sbase + dsto[i], asrc[i], assz[i]);
        cpasync16(sbase + 16384 + dsto[i], bsrc[i], 16);
    }
    CP_COMMIT();

    int li = lane & 3;
    for (int s = 0; s < NS2; s++) {
        if (s + 1 < NS2) {
            uint32_t sb = sbase + ((s + 1) & 1) * STAGE_BYTES;
            int k0 = (s + 1) * 64;
#pragma unroll
            for (int i = 0; i < 4; i++) {
                cpasync16(sb + dsto[i], asrc[i] + k0, assz[i]);
                cpasync16(sb + 16384 + dsto[i], bsrc[i] + k0, 16);
            }
            CP_COMMIT();
            CP_WAIT1();
        } else {
            CP_WAIT0();
        }
        __syncthreads();

        const char* stA = sm + (s & 1) * STAGE_BYTES;
        const char* stB = stA + 16384;
#pragma unroll
        for (int ks = 0; ks < 4; ks++) {
            uint32_t af[2][4];
#pragma unroll
            for (int mt = 0; mt < 2; mt++) {
                int r0 = wm * 32 + mt * 16 + (lane >> 2);
                af[mt][0] = LDH(stA, r0,     ks, li, 0);
                af[mt][1] = LDH(stA, r0 + 8, ks, li, 0);
                af[mt][2] = LDH(stA, r0,     ks, li, 1);
                af[mt][3] = LDH(stA, r0 + 8, ks, li, 1);
            }
#pragma unroll
            for (int nt = 0; nt < 8; nt++) {
                int n = wn * 64 + nt * 8 + (lane >> 2);
                uint32_t bf[2] = { LDH(stB, n, ks, li, 0), LDH(stB, n, ks, li, 1) };
#pragma unroll
                for (int mt = 0; mt < 2; mt++)
                    mma16(acc[mt][nt], af[mt], bf);
            }
        }
        __syncthreads();
    }

    // epilogue: weighted write into per-(token,slot) scratch (fp32)
#pragma unroll
    for (int mt = 0; mt < 2; mt++) {
        int rb = wm * 32 + mt * 16 + (lane >> 2);
#pragma unroll
        for (int half = 0; half < 2; half++) {
            int ridx = rt * 128 + rb + half * 8;
            if (ridx < cnt) {
                float w = g_list_w[e * CAP + ridx];
                int   c = g_list_c[e * CAP + ridx];
                float* yp = g_y + (size_t)c * HID + (size_t)ctn * 128;
#pragma unroll
                for (int nt = 0; nt < 8; nt++) {
                    int cc = wn * 64 + nt * 8 + (lane & 3) * 2;
                    yp[cc]     = w * acc[mt][nt][half * 2 + 0];
                    yp[cc + 1] = w * acc[mt][nt][half * 2 + 1];
                }
            }
        }
    }
}

// ---------------- 4. combine: out[t] = y[2t] + y[2t+1] ----------------
__global__ void combine_kernel(float* __restrict__ out) {
    size_t idx = (size_t)blockIdx.x * blockDim.x + threadIdx.x;
    const size_t n4 = (size_t)NTOK * HID / 4;
    if (idx >= n4) return;
    size_t t = idx / (HID / 4);
    size_t j = idx % (HID / 4);
    const float4* y4 = (const float4*)g_y;
    float4 a = y4[(t * 2) * (HID / 4) + j];
    float4 b = y4[(t * 2 + 1) * (HID / 4) + j];
    float4 o;
    o.x = a.x + b.x; o.y = a.y + b.y; o.z = a.z + b.z; o.w = a.w + b.w;
    ((float4*)out)[idx] = o;
}

// ---------------- launch ----------------
extern "C" void kernel_launch(void* const* d_in, const int* in_sizes, int n_in,
                              void* d_out, int out_size) {
    const float* x   = (const float*)d_in[0];
    const float* gw  = (const float*)d_in[1];
    const float* w13 = (const float*)d_in[2];
    const float* w2  = (const float*)d_in[3];
    float* out = (float*)d_out;

    cudaFuncSetAttribute(gemm1_kernel, cudaFuncAttributeMaxDynamicSharedMemorySize, GEMM_SMEM);
    cudaFuncSetAttribute(gemm2_kernel, cudaFuncAttributeMaxDynamicSharedMemorySize, GEMM_SMEM);

    conv_w13_kernel<<<2048, 256>>>(w13);                        // launch 0
    conv_w2x_kernel<<<2048, 256>>>(w2, x);                      // launch 1
    gate_kernel<<<NTOK / 8, 256>>>(x, gw);                      // launch 2
    gemm1_kernel<<<dim3(INTER / 64, CAP / 128, NE), 256, GEMM_SMEM>>>();  // launch 3 (ncu)
    gemm2_kernel<<<dim3(HID / 128, CAP / 128, NE), 256, GEMM_SMEM>>>();   // launch 4
    combine_kernel<<<(NTOK * HID / 4) / 256, 256>>>(out);       // launch 5
}

// round 8
// speedup vs baseline: 3.0926x; 1.6420x over previous
#include <cuda_runtime.h>
#include <cuda_fp16.h>
#include <cstdint>
#include <cstddef>

#define NE    8
#define HID   2048
#define INTER 2816
#define NTOK  8192
#define MAXENT (NTOK * 2)
#define CAP   16384            // per-expert worst-case rows

// ---------------- scratch (device globals; no runtime allocation) ----------------
__device__ int    g_cursor[NE];
__device__ int    g_list_c[NE * CAP];          // token*2 + slot
__device__ float  g_list_w[NE * CAP];
__device__ __half c_x[(size_t)NTOK * HID];             // fp16 x   (33 MB)
__device__ __half c_w13[(size_t)NE * 2 * INTER * HID]; // fp16 w13 (184 MB)
__device__ __half c_w2[(size_t)NE * HID * INTER];      // fp16 w2  (92 MB)
__device__ __half g_h[(size_t)NE * CAP * INTER];       // fp16 h   (738 MB)
__device__ float  g_y[(size_t)MAXENT * HID];           // fp32 y   (134 MB)

// ---------------- helpers ----------------
__device__ __forceinline__ uint32_t smem_u32(const void* p) {
    uint32_t a;
    asm("{ .reg .u64 t; cvta.to.shared.u64 t, %1; cvt.u32.u64 %0, t; }" : "=r"(a) : "l"(p));
    return a;
}
__device__ __forceinline__ void cpasync16(uint32_t dst, const void* src, int srcsize) {
    asm volatile("cp.async.cg.shared.global [%0], [%1], 16, %2;"
                 :: "r"(dst), "l"(src), "r"(srcsize) : "memory");
}
#define CP_COMMIT() asm volatile("cp.async.commit_group;" ::: "memory")
#define CP_WAIT1()  asm volatile("cp.async.wait_group 1;" ::: "memory")
#define CP_WAIT0()  asm volatile("cp.async.wait_group 0;" ::: "memory")

// fp16 MMA, fp32 accumulate: D(16x8) += A(16x16) * B(8x16)^T
__device__ __forceinline__ void mma16(float* d, const uint32_t* a, const uint32_t* b) {
    asm volatile(
        "mma.sync.aligned.m16n8k16.row.col.f32.f16.f16.f32 "
        "{%0,%1,%2,%3}, {%4,%5,%6,%7}, {%8,%9}, {%0,%1,%2,%3};\n"
        : "+f"(d[0]), "+f"(d[1]), "+f"(d[2]), "+f"(d[3])
        : "r"(a[0]), "r"(a[1]), "r"(a[2]), "r"(a[3]),
          "r"(b[0]), "r"(b[1]));
}

// ldmatrix: 4x (8x8 b16) matrices, one instruction, per-lane row addresses
__device__ __forceinline__ void ldsm4(uint32_t* r, uint32_t addr) {
    asm volatile("ldmatrix.sync.aligned.m8n8.x4.shared.b16 {%0,%1,%2,%3}, [%4];"
                 : "=r"(r[0]), "=r"(r[1]), "=r"(r[2]), "=r"(r[3]) : "r"(addr));
}

__device__ __forceinline__ uint32_t h2u(__half2 h) {
    return *(const uint32_t*)&h;
}

#define STAGE_BYTES 32768      // A 16KB + B 16KB (128 rows x 128B, k-slab = 64 halves)
#define GEMM_SMEM (2 * STAGE_BYTES)   // 64 KB -> 2 CTAs/SM

// ---------------- 0a. convert w13 -> fp16 (+ reset cursors) ----------------
__global__ __launch_bounds__(256) void conv_w13_kernel(const float* __restrict__ w13) {
    if (blockIdx.x == 0 && threadIdx.x < NE) g_cursor[threadIdx.x] = 0;
    const size_t ng = (size_t)NE * 2 * INTER * HID / 8;
    for (size_t g = (size_t)blockIdx.x * blockDim.x + threadIdx.x; g < ng;
         g += (size_t)gridDim.x * blockDim.x) {
        const float4* src = (const float4*)(w13 + g * 8);
        float4 lo = src[0], hi = src[1];
        uint4 o;
        o.x = h2u(__floats2half2_rn(lo.x, lo.y));
        o.y = h2u(__floats2half2_rn(lo.z, lo.w));
        o.z = h2u(__floats2half2_rn(hi.x, hi.y));
        o.w = h2u(__floats2half2_rn(hi.z, hi.w));
        ((uint4*)c_w13)[g] = o;
    }
}

// ---------------- 0b. convert w2 + x -> fp16 ----------------
__global__ __launch_bounds__(256) void conv_w2x_kernel(const float* __restrict__ w2,
                                                       const float* __restrict__ x) {
    const size_t nw = (size_t)NE * HID * INTER / 8;
    for (size_t g = (size_t)blockIdx.x * blockDim.x + threadIdx.x; g < nw;
         g += (size_t)gridDim.x * blockDim.x) {
        const float4* src = (const float4*)(w2 + g * 8);
        float4 lo = src[0], hi = src[1];
        uint4 o;
        o.x = h2u(__floats2half2_rn(lo.x, lo.y));
        o.y = h2u(__floats2half2_rn(lo.z, lo.w));
        o.z = h2u(__floats2half2_rn(hi.x, hi.y));
        o.w = h2u(__floats2half2_rn(hi.z, hi.w));
        ((uint4*)c_w2)[g] = o;
    }
    const size_t nx = (size_t)NTOK * HID / 8;
    for (size_t g = (size_t)blockIdx.x * blockDim.x + threadIdx.x; g < nx;
         g += (size_t)gridDim.x * blockDim.x) {
        const float4* src = (const float4*)(x + g * 8);
        float4 lo = src[0], hi = src[1];
        uint4 o;
        o.x = h2u(__floats2half2_rn(lo.x, lo.y));
        o.y = h2u(__floats2half2_rn(lo.z, lo.w));
        o.z = h2u(__floats2half2_rn(hi.x, hi.y));
        o.w = h2u(__floats2half2_rn(hi.z, hi.w));
        ((uint4*)c_x)[g] = o;
    }
}

// ---------------- 1. gating + scatter (fused, fp32) ----------------
__global__ __launch_bounds__(256) void gate_kernel(const float* __restrict__ x,
                                                   const float* __restrict__ gw) {
    int warp = threadIdx.x >> 5;
    int lane = threadIdx.x & 31;
    int t = blockIdx.x * 8 + warp;
    if (t >= NTOK) return;

    const float4* xp = (const float4*)(x + (size_t)t * HID);
    float acc[NE];
#pragma unroll
    for (int e = 0; e < NE; e++) acc[e] = 0.f;

    for (int kk = 0; kk < HID / 4; kk += 32) {
        float4 xv = xp[kk + lane];
#pragma unroll
        for (int e = 0; e < NE; e++) {
            float4 g = ((const float4*)(gw + (size_t)e * HID))[kk + lane];
            acc[e] += xv.x * g.x + xv.y * g.y + xv.z * g.z + xv.w * g.w;
        }
    }
#pragma unroll
    for (int e = 0; e < NE; e++) {
#pragma unroll
        for (int o = 16; o > 0; o >>= 1)
            acc[e] += __shfl_xor_sync(0xffffffffu, acc[e], o);
    }
    if (lane == 0) {
        float mx = acc[0];
#pragma unroll
        for (int e = 1; e < NE; e++) mx = fmaxf(mx, acc[e]);
        float p[NE], s = 0.f;
#pragma unroll
        for (int e = 0; e < NE; e++) { p[e] = __expf(acc[e] - mx); s += p[e]; }
        float inv = 1.f / s;
        int i0 = 0; float v0 = p[0];
#pragma unroll
        for (int e = 1; e < NE; e++) if (p[e] > v0) { v0 = p[e]; i0 = e; }
        int i1 = -1; float v1 = -1.f;
#pragma unroll
        for (int e = 0; e < NE; e++) if (e != i0 && p[e] > v1) { v1 = p[e]; i1 = e; }
        int pos0 = atomicAdd(&g_cursor[i0], 1);
        g_list_c[i0 * CAP + pos0] = t * 2;
        g_list_w[i0 * CAP + pos0] = v0 * inv;
        int pos1 = atomicAdd(&g_cursor[i1], 1);
        g_list_c[i1 * CAP + pos1] = t * 2 + 1;
        g_list_w[i1 * CAP + pos1] = v1 * inv;
    }
}

// ---------------- 2. GEMM1: h = silu(X Wg^T) * (X Wu^T), fp16 MMA + ldmatrix ----------------
// tile 128 rows x (64 g + 64 u cols); 8 warps 4x2; cp.async 2-stage; k-slab 64.
#define NS1 (HID / 64)   // 32

__global__ __launch_bounds__(256) void gemm1_kernel() {
    int e = blockIdx.z;
    int cnt = g_cursor[e];
    int rt = blockIdx.y;
    if (rt * 128 >= cnt) return;
    int ct = blockIdx.x;

    extern __shared__ char sm[];
    uint32_t sbase = smem_u32(sm);

    int tid = threadIdx.x;
    int lane = tid & 31, wid = tid >> 5;
    int wm = wid >> 1, wn = wid & 1;

    // loader mapping: 4 A-chunks + 4 B-chunks of 16B (8 halves) per thread per slab
    const __half* asrc[4];
    const __half* bsrc[4];
    int assz[4];
    uint32_t dsto[4];
#pragma unroll
    for (int i = 0; i < 4; i++) {
        int idx = i * 256 + tid;
        int r = idx >> 3;            // 0..127
        int q = idx & 7;             // 16B chunk in 128B row
        int ridx = rt * 128 + r;
        int tok = (ridx < cnt) ? (g_list_c[e * CAP + ridx] >> 1) : 0;
        asrc[i] = c_x + (size_t)tok * HID + q * 8;
        assz[i] = (ridx < cnt) ? 16 : 0;
        int grow = (r < 64) ? (ct * 64 + r) : (INTER + ct * 64 + (r - 64));
        bsrc[i] = c_w13 + ((size_t)e * 2 * INTER + grow) * HID + q * 8;
        dsto[i] = (uint32_t)(r * 128 + ((q * 16) ^ ((r & 7) << 4)));
    }

    // ldmatrix per-lane addressing
    int mi = lane >> 3, l7 = lane & 7;
    uint32_t xorv = (uint32_t)(l7 << 4);
    uint32_t aKoff = (uint32_t)((mi >> 1) << 4);   // A: matrices {rows, rows+8} x {k0,k8}
    uint32_t bKoff = (uint32_t)((mi & 1) << 4);    // B: matrices {k0,k8} x {rows, rows+8}
    uint32_t aRowB = (uint32_t)((wm * 32 + ((mi & 1) << 3) + l7) * 128);
    int bRowSel = ((mi >> 1) << 3) + l7;
    uint32_t bgRow[2], buRow[2];
#pragma unroll
    for (int p = 0; p < 2; p++) {
        bgRow[p] = (uint32_t)((wn * 32 + p * 16 + bRowSel) * 128);
        buRow[p] = (uint32_t)((64 + wn * 32 + p * 16 + bRowSel) * 128);
    }

    float cg[2][4][4], cu[2][4][4];
#pragma unroll
    for (int mt = 0; mt < 2; mt++)
#pragma unroll
        for (int nt = 0; nt < 4; nt++)
#pragma unroll
            for (int q = 0; q < 4; q++) { cg[mt][nt][q] = 0.f; cu[mt][nt][q] = 0.f; }

    // prologue: slab 0
#pragma unroll
    for (int i = 0; i < 4; i++) {
        cpasync16(sbase + dsto[i], asrc[i], assz[i]);
        cpasync16(sbase + 16384 + dsto[i], bsrc[i], 16);
    }
    CP_COMMIT();

    for (int s = 0; s < NS1; s++) {
        if (s + 1 < NS1) {
            uint32_t sb = sbase + ((s + 1) & 1) * STAGE_BYTES;
            int k0 = (s + 1) * 64;
#pragma unroll
            for (int i = 0; i < 4; i++) {
                cpasync16(sb + dsto[i], asrc[i] + k0, assz[i]);
                cpasync16(sb + 16384 + dsto[i], bsrc[i] + k0, 16);
            }
            CP_COMMIT();
            CP_WAIT1();
        } else {
            CP_WAIT0();
        }
        __syncthreads();

        uint32_t stA = sbase + ((s & 1) * STAGE_BYTES);
        uint32_t stB = stA + 16384;
#pragma unroll
        for (int ks = 0; ks < 4; ks++) {
            uint32_t aoff = ((uint32_t)(ks * 32) + aKoff) ^ xorv;
            uint32_t boff = ((uint32_t)(ks * 32) + bKoff) ^ xorv;
            uint32_t af[2][4], qg[2][4], qu[2][4];
#pragma unroll
            for (int mt = 0; mt < 2; mt++)
                ldsm4(af[mt], stA + aRowB + (uint32_t)(mt * 2048) + aoff);
#pragma unroll
            for (int p = 0; p < 2; p++) {
                ldsm4(qg[p], stB + bgRow[p] + boff);
                ldsm4(qu[p], stB + buRow[p] + boff);
            }
#pragma unroll
            for (int nt = 0; nt < 4; nt++) {
                int p = nt >> 1, h = (nt & 1) * 2;
                uint32_t bg[2] = { qg[p][h], qg[p][h + 1] };
                uint32_t bu[2] = { qu[p][h], qu[p][h + 1] };
#pragma unroll
                for (int mt = 0; mt < 2; mt++) {
                    mma16(cg[mt][nt], af[mt], bg);
                    mma16(cu[mt][nt], af[mt], bu);
                }
            }
        }
        __syncthreads();
    }

    // epilogue: h = silu(g) * u, stored fp16 (half2 per thread pair)
#pragma unroll
    for (int mt = 0; mt < 2; mt++) {
        int rb = wm * 32 + mt * 16 + (lane >> 2);
#pragma unroll
        for (int half = 0; half < 2; half++) {
            int ridx = rt * 128 + rb + half * 8;
            if (ridx < cnt) {
                __half* hp = g_h + ((size_t)e * CAP + ridx) * INTER + (size_t)ct * 64;
#pragma unroll
                for (int nt = 0; nt < 4; nt++) {
                    int cc = wn * 32 + nt * 8 + (lane & 3) * 2;
                    float gv0 = cg[mt][nt][half * 2 + 0], gv1 = cg[mt][nt][half * 2 + 1];
                    float uv0 = cu[mt][nt][half * 2 + 0], uv1 = cu[mt][nt][half * 2 + 1];
                    float h0 = gv0 * (1.f / (1.f + __expf(-gv0))) * uv0;
                    float h1 = gv1 * (1.f / (1.f + __expf(-gv1))) * uv1;
                    *(__half2*)(hp + cc) = __floats2half2_rn(h0, h1);
                }
            }
        }
    }
}

// ---------------- 3. GEMM2: y[c] = w_c * (h W2^T), fp16 MMA + ldmatrix ----------------
// tile 128x128; 8 warps 4x2, warp 32x64; cp.async 2-stage; k-slab 64.
#define NS2 (INTER / 64)  // 44

__global__ __launch_bounds__(256) void gemm2_kernel() {
    int e = blockIdx.z;
    int cnt = g_cursor[e];
    int rt = blockIdx.y;
    if (rt * 128 >= cnt) return;
    int ctn = blockIdx.x;

    extern __shared__ char sm[];
    uint32_t sbase = smem_u32(sm);

    int tid = threadIdx.x;
    int lane = tid & 31, wid = tid >> 5;
    int wm = wid >> 1, wn = wid & 1;

    const __half* asrc[4];
    const __half* bsrc[4];
    int assz[4];
    uint32_t dsto[4];
#pragma unroll
    for (int i = 0; i < 4; i++) {
        int idx = i * 256 + tid;
        int r = idx >> 3;
        int q = idx & 7;
        int ridx = rt * 128 + r;
        asrc[i] = g_h + ((size_t)e * CAP + ridx) * INTER + q * 8;
        assz[i] = (ridx < cnt) ? 16 : 0;
        bsrc[i] = c_w2 + ((size_t)e * HID + ctn * 128 + r) * INTER + q * 8;
        dsto[i] = (uint32_t)(r * 128 + ((q * 16) ^ ((r & 7) << 4)));
    }

    // ldmatrix per-lane addressing
    int mi = lane >> 3, l7 = lane & 7;
    uint32_t xorv = (uint32_t)(l7 << 4);
    uint32_t aKoff = (uint32_t)((mi >> 1) << 4);
    uint32_t bKoff = (uint32_t)((mi & 1) << 4);
    uint32_t aRowB = (uint32_t)((wm * 32 + ((mi & 1) << 3) + l7) * 128);
    int bRowSel = ((mi >> 1) << 3) + l7;
    uint32_t bRow[4];
#pragma unroll
    for (int p = 0; p < 4; p++)
        bRow[p] = (uint32_t)((wn * 64 + p * 16 + bRowSel) * 128);

    float acc[2][8][4];
#pragma unroll
    for (int mt = 0; mt < 2; mt++)
#pragma unroll
        for (int nt = 0; nt < 8; nt++)
#pragma unroll
            for (int q = 0; q < 4; q++) acc[mt][nt][q] = 0.f;

#pragma unroll
    for (int i = 0; i < 4; i++) {
        cpasync16(sbase + dsto[i], asrc[i], assz[i]);
        cpasync16(sbase + 16384 + dsto[i], bsrc[i], 16);
    }
    CP_COMMIT();

    for (int s = 0; s < NS2; s++) {
        if (s + 1 < NS2) {
            uint32_t sb = sbase + ((s + 1) & 1) * STAGE_BYTES;
            int k0 = (s + 1) * 64;
#pragma unroll
            for (int i = 0; i < 4; i++) {
                cpasync16(sb + dsto[i], asrc[i] + k0, assz[i]);
                cpasync16(sb + 16384 + dsto[i], bsrc[i] + k0, 16);
            }
            CP_COMMIT();
            CP_WAIT1();
        } else {
            CP_WAIT0();
        }
        __syncthreads();

        uint32_t stA = sbase + ((s & 1) * STAGE_BYTES);
        uint32_t stB = stA + 16384;
#pragma unroll
        for (int ks = 0; ks < 4; ks++) {
            uint32_t aoff = ((uint32_t)(ks * 32) + aKoff) ^ xorv;
            uint32_t boff = ((uint32_t)(ks * 32) + bKoff) ^ xorv;
            uint32_t af[2][4], qb[4][4];
#pragma unroll
            for (int mt = 0; mt < 2; mt++)
                ldsm4(af[mt], stA + aRowB + (uint32_t)(mt * 2048) + aoff);
#pragma unroll
            for (int p = 0; p < 4; p++)
                ldsm4(qb[p], stB + bRow[p] + boff);
#pragma unroll
            for (int nt = 0; nt < 8; nt++) {
                int p = nt >> 1, h = (nt & 1) * 2;
                uint32_t bf[2] = { qb[p][h], qb[p][h + 1] };
#pragma unroll
                for (int mt = 0; mt < 2; mt++)
                    mma16(acc[mt][nt], af[mt], bf);
            }
        }
        __syncthreads();
    }

    // epilogue: weighted write into per-(token,slot) scratch (fp32)
#pragma unroll
    for (int mt = 0; mt < 2; mt++) {
        int rb = wm * 32 + mt * 16 + (lane >> 2);
#pragma unroll
        for (int half = 0; half < 2; half++) {
            int ridx = rt * 128 + rb + half * 8;
            if (ridx < cnt) {
                float w = g_list_w[e * CAP + ridx];
                int   c = g_list_c[e * CAP + ridx];
                float* yp = g_y + (size_t)c * HID + (size_t)ctn * 128;
#pragma unroll
                for (int nt = 0; nt < 8; nt++) {
                    int cc = wn * 64 + nt * 8 + (lane & 3) * 2;
                    yp[cc]     = w * acc[mt][nt][half * 2 + 0];
                    yp[cc + 1] = w * acc[mt][nt][half * 2 + 1];
                }
            }
        }
    }
}

// ---------------- 4. combine: out[t] = y[2t] + y[2t+1] ----------------
__global__ void combine_kernel(float* __restrict__ out) {
    size_t idx = (size_t)blockIdx.x * blockDim.x + threadIdx.x;
    const size_t n4 = (size_t)NTOK * HID / 4;
    if (idx >= n4) return;
    size_t t = idx / (HID / 4);
    size_t j = idx % (HID / 4);
    const float4* y4 = (const float4*)g_y;
    float4 a = y4[(t * 2) * (HID / 4) + j];
    float4 b = y4[(t * 2 + 1) * (HID / 4) + j];
    float4 o;
    o.x = a.x + b.x; o.y = a.y + b.y; o.z = a.z + b.z; o.w = a.w + b.w;
    ((float4*)out)[idx] = o;
}

// ---------------- launch ----------------
extern "C" void kernel_launch(void* const* d_in, const int* in_sizes, int n_in,
                              void* d_out, int out_size) {
    const float* x   = (const float*)d_in[0];
    const float* gw  = (const float*)d_in[1];
    const float* w13 = (const float*)d_in[2];
    const float* w2  = (const float*)d_in[3];
    float* out = (float*)d_out;

    cudaFuncSetAttribute(gemm1_kernel, cudaFuncAttributeMaxDynamicSharedMemorySize, GEMM_SMEM);
    cudaFuncSetAttribute(gemm2_kernel, cudaFuncAttributeMaxDynamicSharedMemorySize, GEMM_SMEM);

    conv_w13_kernel<<<2048, 256>>>(w13);                        // launch 0
    conv_w2x_kernel<<<2048, 256>>>(w2, x);                      // launch 1
    gate_kernel<<<NTOK / 8, 256>>>(x, gw);                      // launch 2
    gemm1_kernel<<<dim3(INTER / 64, CAP / 128, NE), 256, GEMM_SMEM>>>();  // launch 3 (ncu)
    gemm2_kernel<<<dim3(HID / 128, CAP / 128, NE), 256, GEMM_SMEM>>>();   // launch 4
    combine_kernel<<<(NTOK * HID / 4) / 256, 256>>>(out);       // launch 5
}